// round 3
// baseline (speedup 1.0000x reference)
#include <cuda_runtime.h>
#include <math.h>

// Global scalar accumulators (no device allocation allowed):
// [0]  reg: sum((F_0g - F_0)^2)
// [1..3]  lcc pair0: sum(dA*dB), sum(dA^2), sum(dB^2)
// [4..6]  lcc pair1: same
// [7,8]   tversky pair0: sum(gt+pred), sum(gt*pred)
// [9,10]  tversky pair1: same
__device__ double g_acc[11];

__global__ void zero_kernel() {
    int t = threadIdx.x;
    if (t < 11) g_acc[t] = 0.0;
}

__device__ __forceinline__ double warp_red(double v) {
#pragma unroll
    for (int o = 16; o > 0; o >>= 1) v += __shfl_down_sync(0xffffffffu, v, o);
    return v;
}

// ---------------------------------------------------------------------------
// Fused LCC kernel: 5x5x5 box mean (zero padding, /125) + global reduction.
// Tile: 32(w) x 16(h), z swept in chunks of 32 slices with a 5-slice ring of
// 2D (5x5) box sums held in registers. Separable: row sums (w) in smem, then
// column sums (h) per thread, then z via the ring.
// ---------------------------------------------------------------------------
#define TW 32
#define TH 16
#define HW 36   // TW + 4 halo
#define HH 20   // TH + 4 halo

__global__ __launch_bounds__(512) void lcc_kernel(
    const float* __restrict__ I0, const float* __restrict__ I0R,
    const float* __restrict__ I1, const float* __restrict__ I1R)
{
    const int pair = blockIdx.z;
    const float* __restrict__ gt = pair ? I1 : I0;
    const float* __restrict__ pr = pair ? I1R : I0R;

    const int bx = blockIdx.x;
    const int wt = bx & 3;          // 4 tiles along W
    const int ht = (bx >> 2) & 7;   // 8 tiles along H
    const int ck = bx >> 5;         // 4 chunks along D
    const int w0 = wt * TW, h0 = ht * TH, d0 = ck * 32;
    const long base = (long)blockIdx.y * (128L * 128L * 128L);  // batch (C=1)

    __shared__ float sA[HH][HW], sB[HH][HW];
    __shared__ float rA[HH][TW], rB[HH][TW];
    __shared__ double red[16][3];

    const int tx = threadIdx.x, ty = threadIdx.y;
    const int tid = ty * TW + tx;

    // ring of 2D box sums over last 5 z-slices (zero-initialized = zero padding)
    float qA0 = 0, qA1 = 0, qA2 = 0, qA3 = 0, qA4 = 0;
    float qB0 = 0, qB1 = 0, qB2 = 0, qB3 = 0, qB4 = 0;
    // center-value delay line (value at slice d-2)
    float cA0 = 0, cA1 = 0, cA2 = 0;
    float cB0 = 0, cB1 = 0, cB2 = 0;

    double aN = 0.0, aG = 0.0, aP = 0.0;

    for (int d = d0 - 2; d <= d0 + 33; ++d) {
        __syncthreads();  // protect smem from previous iteration's readers
        const bool dv = (d >= 0) && (d < 128);
        // load halo slice (zero outside volume)
#pragma unroll
        for (int i = tid; i < HH * HW; i += TW * TH) {
            const int hh = i / HW, ww = i - hh * HW;
            const int gh = h0 + hh - 2, gw = w0 + ww - 2;
            float va = 0.f, vb = 0.f;
            if (dv && gh >= 0 && gh < 128 && gw >= 0 && gw < 128) {
                const long off = base + ((long)d * 128 + gh) * 128 + gw;
                va = gt[off];
                vb = pr[off];
            }
            sA[hh][ww] = va;
            sB[hh][ww] = vb;
        }
        __syncthreads();
        // row sums along w (5-tap)
#pragma unroll
        for (int i = tid; i < HH * TW; i += TW * TH) {
            const int hh = i >> 5, w = i & 31;
            rA[hh][w] = sA[hh][w] + sA[hh][w + 1] + sA[hh][w + 2] + sA[hh][w + 3] + sA[hh][w + 4];
            rB[hh][w] = sB[hh][w] + sB[hh][w + 1] + sB[hh][w + 2] + sB[hh][w + 3] + sB[hh][w + 4];
        }
        __syncthreads();
        // column sums along h (5-tap) -> 2D 5x5 box sum for this slice
        const float nA = rA[ty][tx] + rA[ty + 1][tx] + rA[ty + 2][tx] + rA[ty + 3][tx] + rA[ty + 4][tx];
        const float nB = rB[ty][tx] + rB[ty + 1][tx] + rB[ty + 2][tx] + rB[ty + 3][tx] + rB[ty + 4][tx];
        const float ncA = sA[ty + 2][tx + 2];
        const float ncB = sB[ty + 2][tx + 2];

        // shift rings
        qA0 = qA1; qA1 = qA2; qA2 = qA3; qA3 = qA4; qA4 = nA;
        qB0 = qB1; qB1 = qB2; qB2 = qB3; qB3 = qB4; qB4 = nB;
        cA2 = cA1; cA1 = cA0; cA0 = ncA;
        cB2 = cB1; cB1 = cB0; cB0 = ncB;

        const int dc = d - 2;  // emitted center slice (<= d0+31 < 128 always)
        if (dc >= d0) {
            const float zA = qA0 + qA1 + qA2 + qA3 + qA4;
            const float zB = qB0 + qB1 + qB2 + qB3 + qB4;
            const float dA = cA2 - zA * (1.0f / 125.0f);
            const float dB = cB2 - zB * (1.0f / 125.0f);
            aN += (double)(dA * dB);
            aG += (double)(dA * dA);
            aP += (double)(dB * dB);
        }
    }

    // block reduction -> one atomic per scalar per block
    aN = warp_red(aN); aG = warp_red(aG); aP = warp_red(aP);
    const int wid = tid >> 5, lane = tid & 31;
    if (lane == 0) { red[wid][0] = aN; red[wid][1] = aG; red[wid][2] = aP; }
    __syncthreads();
    if (wid == 0) {
        double vN = (lane < 16) ? red[lane][0] : 0.0;
        double vG = (lane < 16) ? red[lane][1] : 0.0;
        double vP = (lane < 16) ? red[lane][2] : 0.0;
        vN = warp_red(vN); vG = warp_red(vG); vP = warp_red(vP);
        if (lane == 0) {
            atomicAdd(&g_acc[1 + 3 * pair], vN);
            atomicAdd(&g_acc[2 + 3 * pair], vG);
            atomicAdd(&g_acc[3 + 3 * pair], vP);
        }
    }
}

// ---------------------------------------------------------------------------
// Streaming reductions: reg_field_loss sum-of-squares + tversky sums.
// blockIdx.y selects task: 0 = reg, 1 = tversky pair0, 2 = tversky pair1.
// ---------------------------------------------------------------------------
__global__ __launch_bounds__(256) void aux_kernel(
    const float* __restrict__ F0, const float* __restrict__ F0g,
    const float* __restrict__ S0, const float* __restrict__ S0g,
    const float* __restrict__ S1, const float* __restrict__ S1g)
{
    const int task = blockIdx.y;
    __shared__ double red[8][2];
    double s0 = 0.0, s1 = 0.0;

    if (task == 0) {
        const float4* __restrict__ a = (const float4*)F0;
        const float4* __restrict__ b = (const float4*)F0g;
        const int n4 = 12582912 / 4;
        for (int i = blockIdx.x * blockDim.x + threadIdx.x; i < n4;
             i += gridDim.x * blockDim.x) {
            const float4 va = a[i], vb = b[i];
            const float d0 = vb.x - va.x, d1 = vb.y - va.y;
            const float d2 = vb.z - va.z, d3 = vb.w - va.w;
            s0 += (double)(d0 * d0 + d1 * d1 + d2 * d2 + d3 * d3);
        }
    } else {
        const float4* __restrict__ a = (const float4*)(task == 1 ? S0 : S1);
        const float4* __restrict__ b = (const float4*)(task == 1 ? S0g : S1g);
        const int n4 = 4194304 / 4;
        for (int i = blockIdx.x * blockDim.x + threadIdx.x; i < n4;
             i += gridDim.x * blockDim.x) {
            const float4 va = a[i], vb = b[i];
            s0 += (double)((va.x + vb.x) + (va.y + vb.y) + (va.z + vb.z) + (va.w + vb.w));
            s1 += (double)(va.x * vb.x + va.y * vb.y + va.z * vb.z + va.w * vb.w);
        }
    }

    s0 = warp_red(s0); s1 = warp_red(s1);
    const int tid = threadIdx.x, wid = tid >> 5, lane = tid & 31;
    if (lane == 0) { red[wid][0] = s0; red[wid][1] = s1; }
    __syncthreads();
    if (wid == 0) {
        double v0 = (lane < 8) ? red[lane][0] : 0.0;
        double v1 = (lane < 8) ? red[lane][1] : 0.0;
        v0 = warp_red(v0); v1 = warp_red(v1);
        if (lane == 0) {
            if (task == 0) {
                atomicAdd(&g_acc[0], v0);
            } else {
                atomicAdd(&g_acc[7 + 2 * (task - 1)], v0);
                atomicAdd(&g_acc[8 + 2 * (task - 1)], v1);
            }
        }
    }
}

__global__ void finalize_kernel(float* __restrict__ out) {
    // reg_field_loss
    double acc = sqrt(g_acc[0]) / 12582912.0;
#pragma unroll
    for (int k = 0; k < 2; ++k) {
        // lcc: -(1/omega) * (sum(dA*dB))^2 / max(sum(dA^2)*sum(dB^2), 1e-5)
        double num = g_acc[1 + 3 * k];
        num *= num;
        double den = g_acc[2 + 3 * k] * g_acc[3 + 3 * k];
        den = den > 1e-5 ? den : 1e-5;
        acc += 10.0 * (-(num / den) / 4194304.0);
        // tversky: -sum(gt*pred) / max(sum(gt+pred), 1e-5)
        double ta = g_acc[7 + 2 * k];
        ta = ta > 1e-5 ? ta : 1e-5;
        acc += 10.0 * (-(g_acc[8 + 2 * k] / ta));
    }
    out[0] = (float)acc;
}

extern "C" void kernel_launch(void* const* d_in, const int* in_sizes, int n_in,
                              void* d_out, int out_size) {
    const float* F0  = (const float*)d_in[0];
    const float* F0g = (const float*)d_in[1];
    const float* I0  = (const float*)d_in[2];
    const float* I0R = (const float*)d_in[3];
    const float* I1  = (const float*)d_in[4];
    const float* I1R = (const float*)d_in[5];
    const float* S0  = (const float*)d_in[6];
    const float* S0g = (const float*)d_in[7];
    const float* S1  = (const float*)d_in[8];
    const float* S1g = (const float*)d_in[9];

    zero_kernel<<<1, 32>>>();
    // 128 = 4 w-tiles * 8 h-tiles * 4 d-chunks; y = batch(2); z = pair(2)
    lcc_kernel<<<dim3(128, 2, 2), dim3(TW, TH)>>>(I0, I0R, I1, I1R);
    aux_kernel<<<dim3(296, 3, 1), 256>>>(F0, F0g, S0, S0g, S1, S1g);
    finalize_kernel<<<1, 1>>>((float*)d_out);
}

// round 4
// speedup vs baseline: 1.5197x; 1.5197x over previous
#include <cuda_runtime.h>
#include <math.h>

// Per-block partial sums (written unconditionally every call -> no zeroing needed).
// g_part_lcc[lb][0..2] : sum(dA*dB), sum(dA^2), sum(dB^2); lb = (pair*2+batch)*128 + tile
// g_part_aux[ab][0..1] : task = ab/148: 0=reg(sumsq), 1=tversky0, 2=tversky1 (sum, dot)
__device__ double g_part_lcc[512][3];
__device__ double g_part_aux[444][2];

__device__ __forceinline__ float warp_redf(float v) {
#pragma unroll
    for (int o = 16; o > 0; o >>= 1) v += __shfl_down_sync(0xffffffffu, v, o);
    return v;
}
__device__ __forceinline__ double warp_redd(double v) {
#pragma unroll
    for (int o = 16; o > 0; o >>= 1) v += __shfl_down_sync(0xffffffffu, v, o);
    return v;
}

#define TW 32
#define TH 16
#define HW 36   // TW + 4 halo
#define HH 20   // TH + 4 halo

// ---------------------------------------------------------------------------
// Mega kernel. Even blockIdx.x -> LCC tile (fused 5x5x5 box-mean + reduction),
// odd blockIdx.x -> streaming aux reductions (reg sumsq / tversky sums).
// Both are float-accumulated per-thread; doubles appear only at per-block
// partial write-out.
// ---------------------------------------------------------------------------
__global__ __launch_bounds__(512, 2) void mega_kernel(
    const float* __restrict__ F0, const float* __restrict__ F0g,
    const float* __restrict__ I0, const float* __restrict__ I0R,
    const float* __restrict__ I1, const float* __restrict__ I1R,
    const float* __restrict__ S0, const float* __restrict__ S0g,
    const float* __restrict__ S1, const float* __restrict__ S1g)
{
    __shared__ float sA[HH][HW], sB[HH][HW];
    __shared__ float rA[HH][TW], rB[HH][TW];
    __shared__ float redf[16][3];

    const int b = blockIdx.x;
    const int tid = threadIdx.x;
    const int lane = tid & 31, wid = tid >> 5;

    if (b & 1) {
        // ---------------- aux path: streaming reductions ----------------
        const int ab = b >> 1;
        if (ab >= 444) return;
        const int task = ab / 148;
        const int abl = ab - task * 148;
        const int gid = abl * 512 + tid;
        const int stride = 148 * 512;  // 75776 threads per task

        float f0 = 0.f, f1 = 0.f;
        double s0 = 0.0, s1 = 0.0;
        int cnt = 0;

        if (task == 0) {
            const float4* __restrict__ a = (const float4*)F0;
            const float4* __restrict__ c = (const float4*)F0g;
            const int n4 = 12582912 / 4;
#pragma unroll 4
            for (int i = gid; i < n4; i += stride) {
                const float4 va = a[i], vb = c[i];
                const float d0 = vb.x - va.x, d1 = vb.y - va.y;
                const float d2 = vb.z - va.z, d3 = vb.w - va.w;
                f0 += (d0 * d0 + d1 * d1) + (d2 * d2 + d3 * d3);
                if (++cnt == 64) { s0 += (double)f0; f0 = 0.f; cnt = 0; }
            }
        } else {
            const float4* __restrict__ a = (const float4*)(task == 1 ? S0 : S1);
            const float4* __restrict__ c = (const float4*)(task == 1 ? S0g : S1g);
            const int n4 = 4194304 / 4;
#pragma unroll 4
            for (int i = gid; i < n4; i += stride) {
                const float4 va = a[i], vb = c[i];
                f0 += ((va.x + vb.x) + (va.y + vb.y)) + ((va.z + vb.z) + (va.w + vb.w));
                f1 += (va.x * vb.x + va.y * vb.y) + (va.z * vb.z + va.w * vb.w);
                if (++cnt == 64) { s0 += (double)f0; s1 += (double)f1; f0 = f1 = 0.f; cnt = 0; }
            }
        }
        s0 += (double)f0; s1 += (double)f1;

        s0 = warp_redd(s0); s1 = warp_redd(s1);
        __shared__ double redd[16][2];
        if (lane == 0) { redd[wid][0] = s0; redd[wid][1] = s1; }
        __syncthreads();
        if (wid == 0) {
            double v0 = (lane < 16) ? redd[lane][0] : 0.0;
            double v1 = (lane < 16) ? redd[lane][1] : 0.0;
            v0 = warp_redd(v0); v1 = warp_redd(v1);
            if (lane == 0) { g_part_aux[ab][0] = v0; g_part_aux[ab][1] = v1; }
        }
        return;
    }

    // ---------------- LCC path: fused box-mean + reduction ----------------
    const int lb = b >> 1;                 // 0..511
    const int tile = lb & 127;
    const int bi = lb >> 7;                // pair*2 + batch
    const int batch = bi & 1;
    const int pair = bi >> 1;

    const float* __restrict__ gt = pair ? I1 : I0;
    const float* __restrict__ pr = pair ? I1R : I0R;

    const int wt = tile & 3;               // 4 tiles along W
    const int ht = (tile >> 2) & 7;        // 8 tiles along H
    const int ck = tile >> 5;              // 4 chunks along D
    const int w0 = wt * TW, h0 = ht * TH, d0 = ck * 32;
    const long base = (long)batch * (128L * 128L * 128L);

    const int tx = tid & 31, ty = tid >> 5;

    // ring of 2D box sums over last 5 z-slices + center-value delay line
    float qA0 = 0, qA1 = 0, qA2 = 0, qA3 = 0, qA4 = 0;
    float qB0 = 0, qB1 = 0, qB2 = 0, qB3 = 0, qB4 = 0;
    float cA0 = 0, cA1 = 0, cA2 = 0;
    float cB0 = 0, cB1 = 0, cB2 = 0;

    float aN = 0.f, aG = 0.f, aP = 0.f;

    for (int it = 0; it < 36; ++it) {
        const int d = d0 - 2 + it;
        __syncthreads();  // protect smem from previous iteration's readers
        const bool dv = ((unsigned)d < 128u);
#pragma unroll 2
        for (int i = tid; i < HH * HW; i += 512) {
            const int hh = i / HW, ww = i - hh * HW;
            const int gh = h0 + hh - 2, gw = w0 + ww - 2;
            float va = 0.f, vb = 0.f;
            if (dv && (unsigned)gh < 128u && (unsigned)gw < 128u) {
                const long off = base + ((long)d * 128 + gh) * 128 + gw;
                va = gt[off];
                vb = pr[off];
            }
            sA[hh][ww] = va;
            sB[hh][ww] = vb;
        }
        __syncthreads();
#pragma unroll 2
        for (int i = tid; i < HH * TW; i += 512) {
            const int hh = i >> 5, w = i & 31;
            rA[hh][w] = ((sA[hh][w] + sA[hh][w + 1]) + (sA[hh][w + 2] + sA[hh][w + 3])) + sA[hh][w + 4];
            rB[hh][w] = ((sB[hh][w] + sB[hh][w + 1]) + (sB[hh][w + 2] + sB[hh][w + 3])) + sB[hh][w + 4];
        }
        __syncthreads();
        const float nA = ((rA[ty][tx] + rA[ty + 1][tx]) + (rA[ty + 2][tx] + rA[ty + 3][tx])) + rA[ty + 4][tx];
        const float nB = ((rB[ty][tx] + rB[ty + 1][tx]) + (rB[ty + 2][tx] + rB[ty + 3][tx])) + rB[ty + 4][tx];
        const float ncA = sA[ty + 2][tx + 2];
        const float ncB = sB[ty + 2][tx + 2];

        qA0 = qA1; qA1 = qA2; qA2 = qA3; qA3 = qA4; qA4 = nA;
        qB0 = qB1; qB1 = qB2; qB2 = qB3; qB3 = qB4; qB4 = nB;
        cA2 = cA1; cA1 = cA0; cA0 = ncA;
        cB2 = cB1; cB1 = cB0; cB0 = ncB;

        if (it >= 4) {  // emitted center slice dc = d-2 >= d0
            const float zA = ((qA0 + qA1) + (qA2 + qA3)) + qA4;
            const float zB = ((qB0 + qB1) + (qB2 + qB3)) + qB4;
            const float dA = fmaf(zA, -(1.0f / 125.0f), cA2);
            const float dB = fmaf(zB, -(1.0f / 125.0f), cB2);
            aN = fmaf(dA, dB, aN);
            aG = fmaf(dA, dA, aG);
            aP = fmaf(dB, dB, aP);
        }
    }

    aN = warp_redf(aN); aG = warp_redf(aG); aP = warp_redf(aP);
    if (lane == 0) { redf[wid][0] = aN; redf[wid][1] = aG; redf[wid][2] = aP; }
    __syncthreads();
    if (wid == 0) {
        float vN = (lane < 16) ? redf[lane][0] : 0.f;
        float vG = (lane < 16) ? redf[lane][1] : 0.f;
        float vP = (lane < 16) ? redf[lane][2] : 0.f;
        vN = warp_redf(vN); vG = warp_redf(vG); vP = warp_redf(vP);
        if (lane == 0) {
            g_part_lcc[lb][0] = (double)vN;
            g_part_lcc[lb][1] = (double)vG;
            g_part_lcc[lb][2] = (double)vP;
        }
    }
}

// ---------------------------------------------------------------------------
// Finalize: reduce per-block partials and apply the loss formula.
// ---------------------------------------------------------------------------
__global__ __launch_bounds__(512) void finalize_kernel(float* __restrict__ out) {
    __shared__ double acc[11];
    const int t = threadIdx.x;
    const int lane = t & 31;
    if (t < 11) acc[t] = 0.0;
    __syncthreads();

    // lcc partials: 512 entries; pair = t>>8 is warp-uniform (256 % 32 == 0)
    {
        double vN = g_part_lcc[t][0];
        double vG = g_part_lcc[t][1];
        double vP = g_part_lcc[t][2];
        const int pair = t >> 8;
        vN = warp_redd(vN); vG = warp_redd(vG); vP = warp_redd(vP);
        if (lane == 0) {
            atomicAdd(&acc[1 + 3 * pair], vN);
            atomicAdd(&acc[2 + 3 * pair], vG);
            atomicAdd(&acc[3 + 3 * pair], vP);
        }
    }
    // aux partials: 444 entries
    if (t < 444) {
        const int task = t / 148;
        const double v0 = g_part_aux[t][0];
        const double v1 = g_part_aux[t][1];
        if (task == 0) {
            atomicAdd(&acc[0], v0);
        } else {
            atomicAdd(&acc[7 + 2 * (task - 1)], v0);
            atomicAdd(&acc[8 + 2 * (task - 1)], v1);
        }
    }
    __syncthreads();

    if (t == 0) {
        double r = sqrt(acc[0]) / 12582912.0;  // reg_field_loss
#pragma unroll
        for (int k = 0; k < 2; ++k) {
            double num = acc[1 + 3 * k];
            num *= num;
            double den = acc[2 + 3 * k] * acc[3 + 3 * k];
            den = den > 1e-5 ? den : 1e-5;
            r += 10.0 * (-(num / den) / 4194304.0);  // lcc
            double ta = acc[7 + 2 * k];
            ta = ta > 1e-5 ? ta : 1e-5;
            r += 10.0 * (-(acc[8 + 2 * k] / ta));    // tversky
        }
        out[0] = (float)r;
    }
}

extern "C" void kernel_launch(void* const* d_in, const int* in_sizes, int n_in,
                              void* d_out, int out_size) {
    const float* F0  = (const float*)d_in[0];
    const float* F0g = (const float*)d_in[1];
    const float* I0  = (const float*)d_in[2];
    const float* I0R = (const float*)d_in[3];
    const float* I1  = (const float*)d_in[4];
    const float* I1R = (const float*)d_in[5];
    const float* S0  = (const float*)d_in[6];
    const float* S0g = (const float*)d_in[7];
    const float* S1  = (const float*)d_in[8];
    const float* S1g = (const float*)d_in[9];

    // even blocks: 512 lcc tiles; odd blocks: 444 aux blocks (rest idle)
    mega_kernel<<<1024, 512>>>(F0, F0g, I0, I0R, I1, I1R, S0, S0g, S1, S1g);
    finalize_kernel<<<1, 512>>>((float*)d_out);
}

// round 7
// speedup vs baseline: 2.1661x; 1.4253x over previous
#include <cuda_runtime.h>
#include <math.h>

// Per-block partial sums (written unconditionally every call -> no zeroing needed).
// g_part_lcc[lb][0..2] : sum(dA*dB), sum(dA^2), sum(dB^2)
// g_part_aux[ab][0..1] : task = ab/148: 0=reg(sumsq), 1=tversky0, 2=tversky1 (sum, dot)
__device__ double g_part_lcc[512][3];
__device__ double g_part_aux[444][2];
__device__ unsigned int g_count = 0;  // self-resetting arrival counter

#define TOTAL_BLOCKS 1024u

__device__ __forceinline__ float warp_redf(float v) {
#pragma unroll
    for (int o = 16; o > 0; o >>= 1) v += __shfl_down_sync(0xffffffffu, v, o);
    return v;
}
__device__ __forceinline__ double warp_redd(double v) {
#pragma unroll
    for (int o = 16; o > 0; o >>= 1) v += __shfl_down_sync(0xffffffffu, v, o);
    return v;
}

#define TW 32
#define TH 16
#define HW 36   // TW + 4 halo
#define HH 20   // TH + 4 halo

// ---------------------------------------------------------------------------
// Mega kernel. Even blockIdx.x -> LCC tile (fused 5x5x5 box-mean + reduction,
// software-pipelined slice loads), odd blockIdx.x -> streaming aux reductions.
// Last block to arrive performs the final scalar reduction and writes out.
// ---------------------------------------------------------------------------
__global__ __launch_bounds__(512, 2) void mega_kernel(
    const float* __restrict__ F0, const float* __restrict__ F0g,
    const float* __restrict__ I0, const float* __restrict__ I0R,
    const float* __restrict__ I1, const float* __restrict__ I1R,
    const float* __restrict__ S0, const float* __restrict__ S0g,
    const float* __restrict__ S1, const float* __restrict__ S1g,
    float* __restrict__ out)
{
    __shared__ float sA[HH][HW], sB[HH][HW];
    __shared__ float rA[HH][TW], rB[HH][TW];
    __shared__ float redf[16][3];
    __shared__ double redd[16][2];
    __shared__ unsigned s_last;

    const int b = blockIdx.x;
    const int tid = threadIdx.x;
    const int lane = tid & 31, wid = tid >> 5;

    if (b & 1) {
        // ---------------- aux path: streaming reductions ----------------
        const int ab = b >> 1;
        if (ab < 444) {
            const int task = ab / 148;
            const int abl = ab - task * 148;
            const int gid = abl * 512 + tid;
            const int stride = 148 * 512;

            float f0 = 0.f, f1 = 0.f;
            if (task == 0) {
                const float4* __restrict__ a = (const float4*)F0;
                const float4* __restrict__ c = (const float4*)F0g;
                const int n4 = 12582912 / 4;
#pragma unroll 4
                for (int i = gid; i < n4; i += stride) {
                    const float4 va = a[i], vb = c[i];
                    const float d0 = vb.x - va.x, d1 = vb.y - va.y;
                    const float d2 = vb.z - va.z, d3 = vb.w - va.w;
                    f0 += (d0 * d0 + d1 * d1) + (d2 * d2 + d3 * d3);
                }
            } else {
                const float4* __restrict__ a = (const float4*)(task == 1 ? S0 : S1);
                const float4* __restrict__ c = (const float4*)(task == 1 ? S0g : S1g);
                const int n4 = 4194304 / 4;
#pragma unroll 4
                for (int i = gid; i < n4; i += stride) {
                    const float4 va = a[i], vb = c[i];
                    f0 += ((va.x + vb.x) + (va.y + vb.y)) + ((va.z + vb.z) + (va.w + vb.w));
                    f1 += (va.x * vb.x + va.y * vb.y) + (va.z * vb.z + va.w * vb.w);
                }
            }
            double s0 = (double)f0, s1 = (double)f1;
            s0 = warp_redd(s0); s1 = warp_redd(s1);
            if (lane == 0) { redd[wid][0] = s0; redd[wid][1] = s1; }
            __syncthreads();
            if (wid == 0) {
                double v0 = (lane < 16) ? redd[lane][0] : 0.0;
                double v1 = (lane < 16) ? redd[lane][1] : 0.0;
                v0 = warp_redd(v0); v1 = warp_redd(v1);
                if (lane == 0) { g_part_aux[ab][0] = v0; g_part_aux[ab][1] = v1; }
            }
        }
    } else {
        // ---------------- LCC path: fused box-mean + reduction ----------------
        const int lb = b >> 1;                 // 0..511
        const int tile = lb & 127;
        const int bi = lb >> 7;                // pair*2 + batch
        const int batch = bi & 1;
        const int pair = bi >> 1;

        const float* __restrict__ gt = pair ? I1 : I0;
        const float* __restrict__ pr = pair ? I1R : I0R;

        const int wt = tile & 3;               // 4 tiles along W
        const int ht = (tile >> 2) & 7;        // 8 tiles along H
        const int ck = tile >> 5;              // 4 chunks along D
        const int w0 = wt * TW, h0 = ht * TH, d0 = ck * 32;
        const long base = (long)batch * (128L * 128L * 128L);

        const int tx = tid & 31, ty = tid >> 5;

        // --- precompute the two load slots this thread owns (addresses are
        //     slice-invariant except for the d*16384 term) ---
        const int j0 = tid;                    // always < 720
        const int j1 = tid + 512;              // valid if < 720
        const int hh0 = j0 / HW, ww0 = j0 - hh0 * HW;
        const int hh1 = j1 / HW, ww1 = j1 - hh1 * HW;
        const int gh0 = h0 + hh0 - 2, gw0 = w0 + ww0 - 2;
        const int gh1 = h0 + hh1 - 2, gw1 = w0 + ww1 - 2;
        const bool pv0 = ((unsigned)gh0 < 128u) && ((unsigned)gw0 < 128u);
        const bool pv1 = (j1 < HH * HW) && ((unsigned)gh1 < 128u) && ((unsigned)gw1 < 128u);
        const long po0 = base + (long)gh0 * 128 + gw0;
        const long po1 = pv1 ? (base + (long)gh1 * 128 + gw1) : base;

        float* const sAf = &sA[0][0];
        float* const sBf = &sB[0][0];

        // ring of 2D box sums + center delay line
        float qA0 = 0, qA1 = 0, qA2 = 0, qA3 = 0, qA4 = 0;
        float qB0 = 0, qB1 = 0, qB2 = 0, qB3 = 0, qB4 = 0;
        float cA0 = 0, cA1 = 0, cA2 = 0;
        float cB0 = 0, cB1 = 0, cB2 = 0;
        float aN = 0.f, aG = 0.f, aP = 0.f;

        // prefetch first slice (d = d0-2)
        float pa0, pb0, pa1, pb1;
        {
            const int d = d0 - 2;
            const bool dv = ((unsigned)d < 128u);
            const long zoff = (long)d * 16384;
            pa0 = (dv && pv0) ? gt[po0 + zoff] : 0.f;
            pb0 = (dv && pv0) ? pr[po0 + zoff] : 0.f;
            pa1 = (dv && pv1) ? gt[po1 + zoff] : 0.f;
            pb1 = (dv && pv1) ? pr[po1 + zoff] : 0.f;
        }

        for (int it = 0; it < 36; ++it) {
            __syncthreads();  // previous iteration's smem consumers done
            // store prefetched slice
            sAf[j0] = pa0; sBf[j0] = pb0;
            if (j1 < HH * HW) { sAf[j1] = pa1; sBf[j1] = pb1; }
            // issue loads for next slice (latency hidden behind row/col stages)
            if (it < 35) {
                const int dn = d0 - 1 + it;
                const bool dv = ((unsigned)dn < 128u);
                const long zoff = (long)dn * 16384;
                pa0 = (dv && pv0) ? gt[po0 + zoff] : 0.f;
                pb0 = (dv && pv0) ? pr[po0 + zoff] : 0.f;
                pa1 = (dv && pv1) ? gt[po1 + zoff] : 0.f;
                pb1 = (dv && pv1) ? pr[po1 + zoff] : 0.f;
            }
            __syncthreads();
            // row sums along w (5-tap)
#pragma unroll 2
            for (int i = tid; i < HH * TW; i += 512) {
                const int hh = i >> 5, w = i & 31;
                rA[hh][w] = ((sA[hh][w] + sA[hh][w + 1]) + (sA[hh][w + 2] + sA[hh][w + 3])) + sA[hh][w + 4];
                rB[hh][w] = ((sB[hh][w] + sB[hh][w + 1]) + (sB[hh][w + 2] + sB[hh][w + 3])) + sB[hh][w + 4];
            }
            __syncthreads();
            // column sums along h (5-tap)
            const float nA = ((rA[ty][tx] + rA[ty + 1][tx]) + (rA[ty + 2][tx] + rA[ty + 3][tx])) + rA[ty + 4][tx];
            const float nB = ((rB[ty][tx] + rB[ty + 1][tx]) + (rB[ty + 2][tx] + rB[ty + 3][tx])) + rB[ty + 4][tx];
            const float ncA = sA[ty + 2][tx + 2];
            const float ncB = sB[ty + 2][tx + 2];

            qA0 = qA1; qA1 = qA2; qA2 = qA3; qA3 = qA4; qA4 = nA;
            qB0 = qB1; qB1 = qB2; qB2 = qB3; qB3 = qB4; qB4 = nB;
            cA2 = cA1; cA1 = cA0; cA0 = ncA;
            cB2 = cB1; cB1 = cB0; cB0 = ncB;

            if (it >= 4) {
                const float zA = ((qA0 + qA1) + (qA2 + qA3)) + qA4;
                const float zB = ((qB0 + qB1) + (qB2 + qB3)) + qB4;
                const float dA = fmaf(zA, -(1.0f / 125.0f), cA2);
                const float dB = fmaf(zB, -(1.0f / 125.0f), cB2);
                aN = fmaf(dA, dB, aN);
                aG = fmaf(dA, dA, aG);
                aP = fmaf(dB, dB, aP);
            }
        }

        aN = warp_redf(aN); aG = warp_redf(aG); aP = warp_redf(aP);
        if (lane == 0) { redf[wid][0] = aN; redf[wid][1] = aG; redf[wid][2] = aP; }
        __syncthreads();
        if (wid == 0) {
            float vN = (lane < 16) ? redf[lane][0] : 0.f;
            float vG = (lane < 16) ? redf[lane][1] : 0.f;
            float vP = (lane < 16) ? redf[lane][2] : 0.f;
            vN = warp_redf(vN); vG = warp_redf(vG); vP = warp_redf(vP);
            if (lane == 0) {
                g_part_lcc[lb][0] = (double)vN;
                g_part_lcc[lb][1] = (double)vG;
                g_part_lcc[lb][2] = (double)vP;
            }
        }
    }

    // ---------------- arrival + last-block finalization ----------------
    __syncthreads();  // all partial writes in this block issued
    if (tid == 0) {
        __threadfence();
        const unsigned old = atomicAdd(&g_count, 1u);
        const unsigned last = (old == TOTAL_BLOCKS - 1u);
        s_last = last;
        if (last) g_count = 0u;  // self-reset for next graph replay
    }
    __syncthreads();
    if (!s_last) return;

    // last block: reduce all partials and apply the loss formula
    __shared__ double facc[11];
    if (tid < 11) facc[tid] = 0.0;
    __syncthreads();
    {
        double vN = g_part_lcc[tid][0];
        double vG = g_part_lcc[tid][1];
        double vP = g_part_lcc[tid][2];
        const int pair = tid >> 8;  // warp-uniform
        vN = warp_redd(vN); vG = warp_redd(vG); vP = warp_redd(vP);
        if (lane == 0) {
            atomicAdd(&facc[1 + 3 * pair], vN);
            atomicAdd(&facc[2 + 3 * pair], vG);
            atomicAdd(&facc[3 + 3 * pair], vP);
        }
    }
    if (tid < 444) {
        const int task = tid / 148;
        const double v0 = g_part_aux[tid][0];
        const double v1 = g_part_aux[tid][1];
        if (task == 0) {
            atomicAdd(&facc[0], v0);
        } else {
            atomicAdd(&facc[7 + 2 * (task - 1)], v0);
            atomicAdd(&facc[8 + 2 * (task - 1)], v1);
        }
    }
    __syncthreads();
    if (tid == 0) {
        double r = sqrt(facc[0]) / 12582912.0;  // reg_field_loss
#pragma unroll
        for (int k = 0; k < 2; ++k) {
            double num = facc[1 + 3 * k];
            num *= num;
            double den = facc[2 + 3 * k] * facc[3 + 3 * k];
            den = den > 1e-5 ? den : 1e-5;
            r += 10.0 * (-(num / den) / 4194304.0);  // lcc
            double ta = facc[7 + 2 * k];
            ta = ta > 1e-5 ? ta : 1e-5;
            r += 10.0 * (-(facc[8 + 2 * k] / ta));   // tversky
        }
        out[0] = (float)r;
    }
}

extern "C" void kernel_launch(void* const* d_in, const int* in_sizes, int n_in,
                              void* d_out, int out_size) {
    const float* F0  = (const float*)d_in[0];
    const float* F0g = (const float*)d_in[1];
    const float* I0  = (const float*)d_in[2];
    const float* I0R = (const float*)d_in[3];
    const float* I1  = (const float*)d_in[4];
    const float* I1R = (const float*)d_in[5];
    const float* S0  = (const float*)d_in[6];
    const float* S0g = (const float*)d_in[7];
    const float* S1  = (const float*)d_in[8];
    const float* S1g = (const float*)d_in[9];

    mega_kernel<<<TOTAL_BLOCKS, 512>>>(F0, F0g, I0, I0R, I1, I1R,
                                       S0, S0g, S1, S1g, (float*)d_out);
}